// round 1
// baseline (speedup 1.0000x reference)
#include <cuda_runtime.h>
#include <math.h>

#define BB 2
#define TT 2048
#define DD 1024
#define HH 16
#define DH 64
#define BT (BB*TT)

// Scratch (allocation-free rule: __device__ globals)
__device__ float g_qkv[(size_t)BT * 3 * DD];   // 48 MB
__device__ float g_q[(size_t)BT * DD];          // 16 MB, [B,H,T,DH]
__device__ float g_k[(size_t)BT * DD];
__device__ float g_v[(size_t)BT * DD];
__device__ float g_att[(size_t)BT * DD];        // [B*T, D]

// ---------------------------------------------------------------------------
// SGEMM: C[M,N] = A[M,K] @ B[K,N] + bias[N].  128x128 block, BK=8, 256 thr.
// M,N,K all multiples of 128/8 here, so no bounds checks.
// ---------------------------------------------------------------------------
__global__ __launch_bounds__(256)
void sgemm_bias_kernel(const float* __restrict__ A, const float* __restrict__ B,
                       const float* __restrict__ bias, float* __restrict__ C,
                       int M, int N, int K) {
    const int BM = 128, BN = 128, BK = 8;
    __shared__ float As[BK][BM];
    __shared__ float Bs[BK][BN];

    int tid  = threadIdx.x;
    int brow = blockIdx.y * BM;
    int bcol = blockIdx.x * BN;

    int trow = (tid / 16) * 8;
    int tcol = (tid % 16) * 8;

    float acc[8][8];
#pragma unroll
    for (int i = 0; i < 8; i++)
#pragma unroll
        for (int j = 0; j < 8; j++) acc[i][j] = 0.f;

    // A tile load mapping: 128 rows x 8 cols, each thread one float4
    int arow = tid / 2;
    int acol = (tid % 2) * 4;
    // B tile load mapping: 8 rows x 128 cols, each thread one float4
    int brw = tid / 32;
    int bcl = (tid % 32) * 4;

    const float* Aptr = A + (size_t)(brow + arow) * K + acol;
    const float* Bptr = B + (size_t)brw * N + bcol + bcl;

    for (int k0 = 0; k0 < K; k0 += BK) {
        float4 av = *(const float4*)(Aptr + k0);
        As[acol + 0][arow] = av.x;
        As[acol + 1][arow] = av.y;
        As[acol + 2][arow] = av.z;
        As[acol + 3][arow] = av.w;
        float4 bv = *(const float4*)(Bptr + (size_t)k0 * N);
        *(float4*)&Bs[brw][bcl] = bv;
        __syncthreads();

#pragma unroll
        for (int kk = 0; kk < BK; kk++) {
            float ra[8], rb[8];
#pragma unroll
            for (int i = 0; i < 8; i++) ra[i] = As[kk][trow + i];
#pragma unroll
            for (int j = 0; j < 8; j++) rb[j] = Bs[kk][tcol + j];
#pragma unroll
            for (int i = 0; i < 8; i++)
#pragma unroll
                for (int j = 0; j < 8; j++) acc[i][j] += ra[i] * rb[j];
        }
        __syncthreads();
    }

#pragma unroll
    for (int i = 0; i < 8; i++) {
        float* crow = C + (size_t)(brow + trow + i) * N + bcol + tcol;
#pragma unroll
        for (int j = 0; j < 8; j++) crow[j] = acc[i][j] + bias[bcol + tcol + j];
    }
}

// ---------------------------------------------------------------------------
// RoPE + split qkv[BT, 3D] -> Q,K,V in [B,H,T,DH]. One thread per (b,t,h,pair)
// ---------------------------------------------------------------------------
__global__ __launch_bounds__(256)
void rope_split_kernel(const float* __restrict__ qkv,
                       float* __restrict__ Q, float* __restrict__ K,
                       float* __restrict__ V) {
    int idx = blockIdx.x * blockDim.x + threadIdx.x;
    const int total = BB * TT * HH * (DH / 2);
    if (idx >= total) return;
    int d2 = idx & 31;              // pair index 0..31
    int h  = (idx >> 5) & (HH - 1);
    int t  = (idx >> 9) & (TT - 1);
    int b  = idx >> 20;

    size_t row = (size_t)b * TT + t;
    const float* qr = qkv + row * (3 * DD) + h * DH + 2 * d2;
    const float* kr = qr + DD;
    const float* vr = qr + 2 * DD;

    float inv_freq = powf(10000.0f, -((float)(2 * d2)) / (float)DH);
    float freq = (float)t * inv_freq;
    float s, c;
    __sincosf(freq, &s, &c);
    // use accurate versions (sincosf): precision matters vs fp32 reference
    s = sinf(freq);
    c = cosf(freq);

    float qe = qr[0], qo = qr[1];
    float ke = kr[0], ko = kr[1];

    size_t o = ((((size_t)b * HH + h) * TT) + t) * DH + 2 * d2;
    Q[o]     = qe * c - qo * s;
    Q[o + 1] = qe * s + qo * c;
    K[o]     = ke * c - ko * s;
    K[o + 1] = ke * s + ko * c;
    V[o]     = vr[0];
    V[o + 1] = vr[1];
}

// ---------------------------------------------------------------------------
// Causal flash attention, fp32, online softmax.
// Block = 64 threads, each thread owns one query row. grid (T/64, H, B).
// K/V tiles (64 x 64) staged in shared; broadcast LDS reads in inner loop.
// ---------------------------------------------------------------------------
__global__ __launch_bounds__(64)
void flash_attn_kernel(const float* __restrict__ Q, const float* __restrict__ K,
                       const float* __restrict__ V, const int* __restrict__ mask,
                       float* __restrict__ Out) {
    int b = blockIdx.z;
    int h = blockIdx.y;
    int qbase = blockIdx.x * 64;
    int i = qbase + threadIdx.x;

    const size_t bh = ((size_t)b * HH + h) * TT;
    const float* Qb = Q + bh * DH;
    const float* Kb = K + bh * DH;
    const float* Vb = V + bh * DH;

    __shared__ float Ks[64 * DH];
    __shared__ float Vs[64 * DH];
    __shared__ int   ms[64];

    float q[DH], o[DH];
#pragma unroll
    for (int d = 0; d < DH; d++) {
        q[d] = Qb[(size_t)i * DH + d];
        o[d] = 0.f;
    }
    float m = -INFINITY, l = 0.f;

    for (int kt = 0; kt <= qbase; kt += 64) {
        // cooperative tile load, coalesced
        for (int idx = threadIdx.x; idx < 64 * DH; idx += 64) {
            Ks[idx] = Kb[(size_t)kt * DH + idx];
            Vs[idx] = Vb[(size_t)kt * DH + idx];
        }
        ms[threadIdx.x] = mask[b * TT + kt + threadIdx.x];
        __syncthreads();

        int jmax = i - kt + 1;
        if (jmax > 64) jmax = 64;
        for (int j = 0; j < jmax; j++) {
            if (!ms[j]) continue;
            const float* krow = &Ks[j * DH];
            float s = 0.f;
#pragma unroll
            for (int d = 0; d < DH; d++) s += q[d] * krow[d];
            s *= 0.125f;  // 1/sqrt(64)

            float p;
            if (s > m) {
                float corr = expf(m - s);   // m=-inf first time -> corr=0
                l *= corr;
#pragma unroll
                for (int d = 0; d < DH; d++) o[d] *= corr;
                m = s;
                p = 1.0f;
            } else {
                p = expf(s - m);
            }
            l += p;
            const float* vrow = &Vs[j * DH];
#pragma unroll
            for (int d = 0; d < DH; d++) o[d] += p * vrow[d];
        }
        __syncthreads();
    }

    float inv = (l > 0.f) ? 1.0f / l : 0.f;
    float* op = Out + ((size_t)b * TT + i) * DD + h * DH;
#pragma unroll
    for (int d = 0; d < DH; d++) op[d] = o[d] * inv;
}

// ---------------------------------------------------------------------------
extern "C" void kernel_launch(void* const* d_in, const int* in_sizes, int n_in,
                              void* d_out, int out_size) {
    const float* x     = (const float*)d_in[0];
    const int*   amask = (const int*)d_in[1];
    const float* Wqkv  = (const float*)d_in[2];
    const float* bqkv  = (const float*)d_in[3];
    const float* Wout  = (const float*)d_in[4];
    const float* bout  = (const float*)d_in[5];
    float* out = (float*)d_out;

    float *qkv, *Qp, *Kp, *Vp, *Att;
    cudaGetSymbolAddress((void**)&qkv, g_qkv);
    cudaGetSymbolAddress((void**)&Qp,  g_q);
    cudaGetSymbolAddress((void**)&Kp,  g_k);
    cudaGetSymbolAddress((void**)&Vp,  g_v);
    cudaGetSymbolAddress((void**)&Att, g_att);

    // 1) QKV projection: [4096,1024]@[1024,3072]
    {
        dim3 grid(3 * DD / 128, BT / 128);
        sgemm_bias_kernel<<<grid, 256>>>(x, Wqkv, bqkv, qkv, BT, 3 * DD, DD);
    }
    // 2) RoPE + split
    {
        int total = BB * TT * HH * (DH / 2);
        rope_split_kernel<<<(total + 255) / 256, 256>>>(qkv, Qp, Kp, Vp);
    }
    // 3) Flash attention
    {
        dim3 grid(TT / 64, HH, BB);
        flash_attn_kernel<<<grid, 64>>>(Qp, Kp, Vp, amask, Att);
    }
    // 4) Output projection: [4096,1024]@[1024,1024]
    {
        dim3 grid(DD / 128, BT / 128);
        sgemm_bias_kernel<<<grid, 256>>>(Att, Wout, bout, out, BT, DD, DD);
    }
}

// round 2
// speedup vs baseline: 1.3560x; 1.3560x over previous
#include <cuda_runtime.h>
#include <math.h>

#define BB 2
#define TT 2048
#define DD 1024
#define HH 16
#define DH 64
#define BT (BB*TT)

// Scratch (allocation-free rule: __device__ globals)
__device__ float g_qkv[(size_t)BT * 3 * DD];
__device__ float g_q[(size_t)BT * DD];   // [B,H,T,DH]
__device__ float g_k[(size_t)BT * DD];
__device__ float g_v[(size_t)BT * DD];
__device__ float g_att[(size_t)BT * DD]; // [B*T, D]

// ---------------------------------------------------------------------------
// SGEMM: C[M,N] = A[M,K] @ B[K,N] + bias[N]. 128x128 block, BK=8, 256 thr.
// ---------------------------------------------------------------------------
__global__ __launch_bounds__(256)
void sgemm_bias_kernel(const float* __restrict__ A, const float* __restrict__ B,
                       const float* __restrict__ bias, float* __restrict__ C,
                       int M, int N, int K) {
    const int BM = 128, BN = 128, BK = 8;
    __shared__ float As[BK][BM];
    __shared__ float Bs[BK][BN];

    int tid  = threadIdx.x;
    int brow = blockIdx.y * BM;
    int bcol = blockIdx.x * BN;

    int trow = (tid / 16) * 8;
    int tcol = (tid % 16) * 8;

    float acc[8][8];
#pragma unroll
    for (int i = 0; i < 8; i++)
#pragma unroll
        for (int j = 0; j < 8; j++) acc[i][j] = 0.f;

    int arow = tid / 2;
    int acol = (tid % 2) * 4;
    int brw = tid / 32;
    int bcl = (tid % 32) * 4;

    const float* Aptr = A + (size_t)(brow + arow) * K + acol;
    const float* Bptr = B + (size_t)brw * N + bcol + bcl;

    for (int k0 = 0; k0 < K; k0 += BK) {
        float4 av = *(const float4*)(Aptr + k0);
        As[acol + 0][arow] = av.x;
        As[acol + 1][arow] = av.y;
        As[acol + 2][arow] = av.z;
        As[acol + 3][arow] = av.w;
        float4 bv = *(const float4*)(Bptr + (size_t)k0 * N);
        *(float4*)&Bs[brw][bcl] = bv;
        __syncthreads();

#pragma unroll
        for (int kk = 0; kk < BK; kk++) {
            float ra[8], rb[8];
#pragma unroll
            for (int i = 0; i < 8; i++) ra[i] = As[kk][trow + i];
#pragma unroll
            for (int j = 0; j < 8; j++) rb[j] = Bs[kk][tcol + j];
#pragma unroll
            for (int i = 0; i < 8; i++)
#pragma unroll
                for (int j = 0; j < 8; j++) acc[i][j] += ra[i] * rb[j];
        }
        __syncthreads();
    }

#pragma unroll
    for (int i = 0; i < 8; i++) {
        float* crow = C + (size_t)(brow + trow + i) * N + bcol + tcol;
#pragma unroll
        for (int j = 0; j < 8; j++) crow[j] = acc[i][j] + bias[bcol + tcol + j];
    }
}

// ---------------------------------------------------------------------------
// RoPE + split qkv[BT, 3D] -> Q,K,V in [B,H,T,DH]
// ---------------------------------------------------------------------------
__global__ __launch_bounds__(256)
void rope_split_kernel(const float* __restrict__ qkv,
                       float* __restrict__ Q, float* __restrict__ K,
                       float* __restrict__ V) {
    int idx = blockIdx.x * blockDim.x + threadIdx.x;
    const int total = BB * TT * HH * (DH / 2);
    if (idx >= total) return;
    int d2 = idx & 31;
    int h  = (idx >> 5) & (HH - 1);
    int t  = (idx >> 9) & (TT - 1);
    int b  = idx >> 20;

    size_t row = (size_t)b * TT + t;
    const float* qr = qkv + row * (3 * DD) + h * DH + 2 * d2;
    const float* kr = qr + DD;
    const float* vr = qr + 2 * DD;

    float inv_freq = powf(10000.0f, -((float)(2 * d2)) / (float)DH);
    float freq = (float)t * inv_freq;
    float s = sinf(freq);
    float c = cosf(freq);

    float qe = qr[0], qo = qr[1];
    float ke = kr[0], ko = kr[1];

    size_t o = ((((size_t)b * HH + h) * TT) + t) * DH + 2 * d2;
    Q[o]     = qe * c - qo * s;
    Q[o + 1] = qe * s + qo * c;
    K[o]     = ke * c - ko * s;
    K[o + 1] = ke * s + ko * c;
    V[o]     = vr[0];
    V[o + 1] = vr[1];
}

// ---------------------------------------------------------------------------
// Tiled flash attention: 64-query tile per block, 256 threads.
// S = Q*K^T and O += P*V both as 64x64x64 register-blocked tile GEMMs.
// Online softmax with 16-lane shfl butterflies; row stats in registers.
// Smem: Qs [64][65] (transposed, prescaled), KPs [64][65] (K^T then P),
//       Vs [64][68] (natural, float4-aligned), ms[64].
// ---------------------------------------------------------------------------
#define QS_STRIDE 65
#define VS_STRIDE 68
#define SMEM_FLASH ((2 * 64 * QS_STRIDE + 64 * VS_STRIDE) * 4 + 64 * 4)

__device__ __forceinline__ void load_tile_T(const float* __restrict__ src,
                                            float* __restrict__ dst,
                                            int tid, float mul) {
    // src: 64x64 row-major -> dst[c*65 + r] = src[r*64 + c] * mul
    int r = tid >> 2;
    int cbase = (tid & 3) * 4;
#pragma unroll
    for (int rep = 0; rep < 4; rep++) {
        int c = cbase + rep * 16;
        float4 v = *(const float4*)(src + r * 64 + c);
        dst[(c + 0) * QS_STRIDE + r] = v.x * mul;
        dst[(c + 1) * QS_STRIDE + r] = v.y * mul;
        dst[(c + 2) * QS_STRIDE + r] = v.z * mul;
        dst[(c + 3) * QS_STRIDE + r] = v.w * mul;
    }
}

__global__ __launch_bounds__(256)
void flash_attn_tiled(const float* __restrict__ Q, const float* __restrict__ K,
                      const float* __restrict__ V, const int* __restrict__ mask,
                      float* __restrict__ Out) {
    extern __shared__ float sm[];
    float* Qs  = sm;                        // [64][65]
    float* KPs = sm + 64 * QS_STRIDE;       // [64][65]: Ks[kk][j] then Ps[i][j]
    float* Vs  = sm + 2 * 64 * QS_STRIDE;   // [64][68]
    int*   ms  = (int*)(sm + 2 * 64 * QS_STRIDE + 64 * VS_STRIDE);

    int b = blockIdx.z, h = blockIdx.y;
    int qtile = gridDim.x - 1 - blockIdx.x;   // heavy tiles scheduled first
    int qbase = qtile * 64;
    int tid = threadIdx.x;
    int ty = tid >> 4;           // 0..15 -> 4 query rows each
    int tx = tid & 15;           // 0..15 -> 4 cols each

    const size_t bh = ((size_t)b * HH + h) * TT;
    const float* Qb = Q + bh * DH;
    const float* Kb = K + bh * DH;
    const float* Vb = V + bh * DH;

    // Load Q tile (transposed, prescaled by 1/sqrt(64))
    load_tile_T(Qb + (size_t)qbase * DH, Qs, tid, 0.125f);

    float acc_o[4][4];
    float m_r[4], l_r[4];
#pragma unroll
    for (int i = 0; i < 4; i++) {
        m_r[i] = -1e30f;
        l_r[i] = 0.f;
#pragma unroll
        for (int j = 0; j < 4; j++) acc_o[i][j] = 0.f;
    }

    for (int kt = 0; kt <= qbase; kt += 64) {
        __syncthreads();   // prior-tile readers of KPs/Vs done

        // Load K tile transposed, V tile natural, mask
        load_tile_T(Kb + (size_t)kt * DH, KPs, tid, 1.0f);
        {
            int j = tid >> 4;
            int c = (tid & 15) * 4;
#pragma unroll
            for (int rep = 0; rep < 4; rep++) {
                float4 v = *(const float4*)(Vb + (size_t)(kt + j + rep * 16) * DH + c);
                *(float4*)&Vs[(j + rep * 16) * VS_STRIDE + c] = v;
            }
        }
        if (tid < 64) ms[tid] = mask[b * TT + kt + tid];
        __syncthreads();

        // S = Q * K^T  (64x64x64)
        float acc_s[4][4];
#pragma unroll
        for (int i = 0; i < 4; i++)
#pragma unroll
            for (int j = 0; j < 4; j++) acc_s[i][j] = 0.f;

        for (int kk = 0; kk < 64; kk++) {
            float ra[4], rb[4];
#pragma unroll
            for (int i = 0; i < 4; i++) ra[i] = Qs[kk * QS_STRIDE + ty * 4 + i];
#pragma unroll
            for (int j = 0; j < 4; j++) rb[j] = KPs[kk * QS_STRIDE + tx * 4 + j];
#pragma unroll
            for (int i = 0; i < 4; i++)
#pragma unroll
                for (int j = 0; j < 4; j++) acc_s[i][j] += ra[i] * rb[j];
        }
        __syncthreads();   // done reading Ks before Ps overwrites it

        bool diag = (kt == qbase);

        // Online softmax; p overwrites acc_s
#pragma unroll
        for (int i = 0; i < 4; i++) {
            int il = ty * 4 + i;
            float rmax = -1e30f;
#pragma unroll
            for (int j = 0; j < 4; j++) {
                int jl = tx * 4 + j;
                bool ok = (ms[jl] != 0) && (!diag || jl <= il);
                float s = ok ? acc_s[i][j] : -1e30f;
                acc_s[i][j] = s;
                rmax = fmaxf(rmax, s);
            }
#pragma unroll
            for (int off = 8; off >= 1; off >>= 1)
                rmax = fmaxf(rmax, __shfl_xor_sync(0xffffffffu, rmax, off, 16));
            float m_new = fmaxf(m_r[i], rmax);
            float rsum = 0.f;
#pragma unroll
            for (int j = 0; j < 4; j++) {
                float p = __expf(acc_s[i][j] - m_new);
                acc_s[i][j] = p;
                rsum += p;
            }
#pragma unroll
            for (int off = 8; off >= 1; off >>= 1)
                rsum += __shfl_xor_sync(0xffffffffu, rsum, off, 16);
            float scale = __expf(m_r[i] - m_new);  // finite sentinels: never NaN
            l_r[i] = l_r[i] * scale + rsum;
            m_r[i] = m_new;
#pragma unroll
            for (int j = 0; j < 4; j++) acc_o[i][j] *= scale;
        }

        // Store P into KPs as Ps[i][j]
#pragma unroll
        for (int i = 0; i < 4; i++)
#pragma unroll
            for (int j = 0; j < 4; j++)
                KPs[(ty * 4 + i) * QS_STRIDE + tx * 4 + j] = acc_s[i][j];
        __syncthreads();

        // O += P * V  (64x64x64)
        for (int j = 0; j < 64; j++) {
            float4 vb = *(const float4*)&Vs[j * VS_STRIDE + tx * 4];
            float pa[4];
#pragma unroll
            for (int i = 0; i < 4; i++) pa[i] = KPs[(ty * 4 + i) * QS_STRIDE + j];
#pragma unroll
            for (int i = 0; i < 4; i++) {
                acc_o[i][0] += pa[i] * vb.x;
                acc_o[i][1] += pa[i] * vb.y;
                acc_o[i][2] += pa[i] * vb.z;
                acc_o[i][3] += pa[i] * vb.w;
            }
        }
    }

    // Epilogue: normalize and write [B*T, D] at head offset
#pragma unroll
    for (int i = 0; i < 4; i++) {
        int il = ty * 4 + i;
        float inv = (l_r[i] > 0.f) ? (1.0f / l_r[i]) : 0.f;
        float4 o4;
        o4.x = acc_o[i][0] * inv;
        o4.y = acc_o[i][1] * inv;
        o4.z = acc_o[i][2] * inv;
        o4.w = acc_o[i][3] * inv;
        *(float4*)(Out + ((size_t)(b * TT + qbase + il)) * DD + h * DH + tx * 4) = o4;
    }
}

// ---------------------------------------------------------------------------
extern "C" void kernel_launch(void* const* d_in, const int* in_sizes, int n_in,
                              void* d_out, int out_size) {
    const float* x     = (const float*)d_in[0];
    const int*   amask = (const int*)d_in[1];
    const float* Wqkv  = (const float*)d_in[2];
    const float* bqkv  = (const float*)d_in[3];
    const float* Wout  = (const float*)d_in[4];
    const float* bout  = (const float*)d_in[5];
    float* out = (float*)d_out;

    float *qkv, *Qp, *Kp, *Vp, *Att;
    cudaGetSymbolAddress((void**)&qkv, g_qkv);
    cudaGetSymbolAddress((void**)&Qp,  g_q);
    cudaGetSymbolAddress((void**)&Kp,  g_k);
    cudaGetSymbolAddress((void**)&Vp,  g_v);
    cudaGetSymbolAddress((void**)&Att, g_att);

    static bool attr_set = false;
    if (!attr_set) {
        cudaFuncSetAttribute(flash_attn_tiled,
                             cudaFuncAttributeMaxDynamicSharedMemorySize,
                             SMEM_FLASH);
        attr_set = true;
    }

    // 1) QKV projection
    {
        dim3 grid(3 * DD / 128, BT / 128);
        sgemm_bias_kernel<<<grid, 256>>>(x, Wqkv, bqkv, qkv, BT, 3 * DD, DD);
    }
    // 2) RoPE + split
    {
        int total = BB * TT * HH * (DH / 2);
        rope_split_kernel<<<(total + 255) / 256, 256>>>(qkv, Qp, Kp, Vp);
    }
    // 3) Tiled flash attention
    {
        dim3 grid(TT / 64, HH, BB);
        flash_attn_tiled<<<grid, 256, SMEM_FLASH>>>(Qp, Kp, Vp, amask, Att);
    }
    // 4) Output projection
    {
        dim3 grid(DD / 128, BT / 128);
        sgemm_bias_kernel<<<grid, 256>>>(Att, Wout, bout, out, BT, DD, DD);
    }
}

// round 3
// speedup vs baseline: 1.5108x; 1.1141x over previous
#include <cuda_runtime.h>
#include <math.h>
#include <mma.h>

using namespace nvcuda;

#define BB 2
#define TT 2048
#define DD 1024
#define HH 16
#define DH 64
#define BT (BB*TT)

// Scratch (allocation-free rule: __device__ globals)
__device__ float g_qkv[(size_t)BT * 3 * DD];
__device__ float g_q[(size_t)BT * DD];   // [B,H,T,DH]
__device__ float g_k[(size_t)BT * DD];
__device__ float g_v[(size_t)BT * DD];
__device__ float g_att[(size_t)BT * DD]; // [B*T, D]

// ---------------------------------------------------------------------------
// TF32 tensor-core GEMM: C[M,N] = A[M,K] @ B[K,N] + bias[N]
// 128x128 CTA tile, 8 warps (4x2), warp tile 32x64 = 2x4 wmma 16x16x8 frags.
// BK=16, double-buffered smem with register prefetch.
// ---------------------------------------------------------------------------
#define BMg 128
#define BNg 128
#define BKg 16
#define A_STRIDE (BKg + 4)   // 20, mult of 4
#define B_STRIDE (BNg + 4)   // 132, mult of 4

__global__ __launch_bounds__(256)
void gemm_tf32_bias(const float* __restrict__ A, const float* __restrict__ B,
                    const float* __restrict__ bias, float* __restrict__ C,
                    int M, int N, int K) {
    __shared__ float As[2][BMg][A_STRIDE];
    __shared__ float Bs[2][BKg][B_STRIDE];

    int tid  = threadIdx.x;
    int wid  = tid >> 5;
    int lane = tid & 31;
    int warp_m = wid & 3;        // 0..3 -> 32 rows each
    int warp_n = wid >> 2;       // 0..1 -> 64 cols each
    int brow = blockIdx.y * BMg;
    int bcol = blockIdx.x * BNg;

    // Load mappings
    int a_row = tid >> 1;          // 0..127
    int a_col = (tid & 1) * 8;     // 0 or 8
    int b_row = tid >> 4;          // 0..15
    int b_col = (tid & 15) * 8;    // 0..120

    const float* Ap = A + (size_t)(brow + a_row) * K + a_col;
    const float* Bp = B + (size_t)b_row * N + bcol + b_col;

    wmma::fragment<wmma::accumulator, 16, 16, 8, float> acc[2][4];
#pragma unroll
    for (int i = 0; i < 2; i++)
#pragma unroll
        for (int j = 0; j < 4; j++) wmma::fill_fragment(acc[i][j], 0.0f);

    // Prefetch tile 0
    float4 ra0 = *(const float4*)(Ap + 0);
    float4 ra1 = *(const float4*)(Ap + 4);
    float4 rb0 = *(const float4*)(Bp + 0);
    float4 rb1 = *(const float4*)(Bp + 4);

    *(float4*)&As[0][a_row][a_col]     = ra0;
    *(float4*)&As[0][a_row][a_col + 4] = ra1;
    *(float4*)&Bs[0][b_row][b_col]     = rb0;
    *(float4*)&Bs[0][b_row][b_col + 4] = rb1;
    __syncthreads();

    int buf = 0;
    const int iters = K / BKg;

    for (int it = 0; it < iters; it++) {
        int k_next = (it + 1) * BKg;
        bool have_next = (k_next < K);
        if (have_next) {
            ra0 = *(const float4*)(Ap + k_next);
            ra1 = *(const float4*)(Ap + k_next + 4);
            rb0 = *(const float4*)(Bp + (size_t)k_next * N);
            rb1 = *(const float4*)(Bp + (size_t)k_next * N + 4);
        }

#pragma unroll
        for (int kk = 0; kk < BKg; kk += 8) {
            wmma::fragment<wmma::matrix_a, 16, 16, 8, wmma::precision::tf32, wmma::row_major> af[2];
            wmma::fragment<wmma::matrix_b, 16, 16, 8, wmma::precision::tf32, wmma::row_major> bf[4];
#pragma unroll
            for (int i = 0; i < 2; i++) {
                wmma::load_matrix_sync(af[i], &As[buf][warp_m * 32 + i * 16][kk], A_STRIDE);
#pragma unroll
                for (int t = 0; t < af[i].num_elements; t++)
                    af[i].x[t] = wmma::__float_to_tf32(af[i].x[t]);
            }
#pragma unroll
            for (int j = 0; j < 4; j++) {
                wmma::load_matrix_sync(bf[j], &Bs[buf][kk][warp_n * 64 + j * 16], B_STRIDE);
#pragma unroll
                for (int t = 0; t < bf[j].num_elements; t++)
                    bf[j].x[t] = wmma::__float_to_tf32(bf[j].x[t]);
            }
#pragma unroll
            for (int i = 0; i < 2; i++)
#pragma unroll
                for (int j = 0; j < 4; j++)
                    wmma::mma_sync(acc[i][j], af[i], bf[j], acc[i][j]);
        }

        if (have_next) {
            buf ^= 1;
            *(float4*)&As[buf][a_row][a_col]     = ra0;
            *(float4*)&As[buf][a_row][a_col + 4] = ra1;
            *(float4*)&Bs[buf][b_row][b_col]     = rb0;
            *(float4*)&Bs[buf][b_row][b_col + 4] = rb1;
            __syncthreads();
        }
    }

    // Epilogue: stage each 16x16 fragment through smem, add bias, write global
    __syncthreads();  // mainloop smem reads done; reuse As as staging
    float* stg = &As[0][0][0] + wid * 16 * 24;   // stride 24 (96B, 16B-aligned rows)

    int er = lane >> 1;            // 0..15
    int ec = (lane & 1) * 8;       // 0 or 8
#pragma unroll
    for (int i = 0; i < 2; i++) {
#pragma unroll
        for (int j = 0; j < 4; j++) {
            wmma::store_matrix_sync(stg, acc[i][j], 24, wmma::mem_row_major);
            __syncwarp();
            int gr = brow + warp_m * 32 + i * 16 + er;
            int gc = bcol + warp_n * 64 + j * 16 + ec;
            float4 v0 = *(float4*)&stg[er * 24 + ec];
            float4 v1 = *(float4*)&stg[er * 24 + ec + 4];
            const float4 bb0 = *(const float4*)&bias[gc];
            const float4 bb1 = *(const float4*)&bias[gc + 4];
            v0.x += bb0.x; v0.y += bb0.y; v0.z += bb0.z; v0.w += bb0.w;
            v1.x += bb1.x; v1.y += bb1.y; v1.z += bb1.z; v1.w += bb1.w;
            *(float4*)(C + (size_t)gr * N + gc)     = v0;
            *(float4*)(C + (size_t)gr * N + gc + 4) = v1;
            __syncwarp();
        }
    }
}

// ---------------------------------------------------------------------------
// RoPE + split qkv[BT, 3D] -> Q,K,V in [B,H,T,DH]
// ---------------------------------------------------------------------------
__global__ __launch_bounds__(256)
void rope_split_kernel(const float* __restrict__ qkv,
                       float* __restrict__ Q, float* __restrict__ K,
                       float* __restrict__ V) {
    int idx = blockIdx.x * blockDim.x + threadIdx.x;
    const int total = BB * TT * HH * (DH / 2);
    if (idx >= total) return;
    int d2 = idx & 31;
    int h  = (idx >> 5) & (HH - 1);
    int t  = (idx >> 9) & (TT - 1);
    int b  = idx >> 20;

    size_t row = (size_t)b * TT + t;
    const float* qr = qkv + row * (3 * DD) + h * DH + 2 * d2;
    const float* kr = qr + DD;
    const float* vr = qr + 2 * DD;

    float inv_freq = powf(10000.0f, -((float)(2 * d2)) / (float)DH);
    float freq = (float)t * inv_freq;
    float s = sinf(freq);
    float c = cosf(freq);

    float qe = qr[0], qo = qr[1];
    float ke = kr[0], ko = kr[1];

    size_t o = ((((size_t)b * HH + h) * TT) + t) * DH + 2 * d2;
    Q[o]     = qe * c - qo * s;
    Q[o + 1] = qe * s + qo * c;
    K[o]     = ke * c - ko * s;
    K[o + 1] = ke * s + ko * c;
    V[o]     = vr[0];
    V[o + 1] = vr[1];
}

// ---------------------------------------------------------------------------
// Tiled flash attention: 64-query tile per block, 256 threads. (unchanged R1)
// ---------------------------------------------------------------------------
#define QS_STRIDE 65
#define VS_STRIDE 68
#define SMEM_FLASH ((2 * 64 * QS_STRIDE + 64 * VS_STRIDE) * 4 + 64 * 4)

__device__ __forceinline__ void load_tile_T(const float* __restrict__ src,
                                            float* __restrict__ dst,
                                            int tid, float mul) {
    int r = tid >> 2;
    int cbase = (tid & 3) * 4;
#pragma unroll
    for (int rep = 0; rep < 4; rep++) {
        int c = cbase + rep * 16;
        float4 v = *(const float4*)(src + r * 64 + c);
        dst[(c + 0) * QS_STRIDE + r] = v.x * mul;
        dst[(c + 1) * QS_STRIDE + r] = v.y * mul;
        dst[(c + 2) * QS_STRIDE + r] = v.z * mul;
        dst[(c + 3) * QS_STRIDE + r] = v.w * mul;
    }
}

__global__ __launch_bounds__(256)
void flash_attn_tiled(const float* __restrict__ Q, const float* __restrict__ K,
                      const float* __restrict__ V, const int* __restrict__ mask,
                      float* __restrict__ Out) {
    extern __shared__ float sm[];
    float* Qs  = sm;
    float* KPs = sm + 64 * QS_STRIDE;
    float* Vs  = sm + 2 * 64 * QS_STRIDE;
    int*   ms  = (int*)(sm + 2 * 64 * QS_STRIDE + 64 * VS_STRIDE);

    int b = blockIdx.z, h = blockIdx.y;
    int qtile = gridDim.x - 1 - blockIdx.x;
    int qbase = qtile * 64;
    int tid = threadIdx.x;
    int ty = tid >> 4;
    int tx = tid & 15;

    const size_t bh = ((size_t)b * HH + h) * TT;
    const float* Qb = Q + bh * DH;
    const float* Kb = K + bh * DH;
    const float* Vb = V + bh * DH;

    load_tile_T(Qb + (size_t)qbase * DH, Qs, tid, 0.125f);

    float acc_o[4][4];
    float m_r[4], l_r[4];
#pragma unroll
    for (int i = 0; i < 4; i++) {
        m_r[i] = -1e30f;
        l_r[i] = 0.f;
#pragma unroll
        for (int j = 0; j < 4; j++) acc_o[i][j] = 0.f;
    }

    for (int kt = 0; kt <= qbase; kt += 64) {
        __syncthreads();

        load_tile_T(Kb + (size_t)kt * DH, KPs, tid, 1.0f);
        {
            int j = tid >> 4;
            int c = (tid & 15) * 4;
#pragma unroll
            for (int rep = 0; rep < 4; rep++) {
                float4 v = *(const float4*)(Vb + (size_t)(kt + j + rep * 16) * DH + c);
                *(float4*)&Vs[(j + rep * 16) * VS_STRIDE + c] = v;
            }
        }
        if (tid < 64) ms[tid] = mask[b * TT + kt + tid];
        __syncthreads();

        float acc_s[4][4];
#pragma unroll
        for (int i = 0; i < 4; i++)
#pragma unroll
            for (int j = 0; j < 4; j++) acc_s[i][j] = 0.f;

        for (int kk = 0; kk < 64; kk++) {
            float ra[4], rb[4];
#pragma unroll
            for (int i = 0; i < 4; i++) ra[i] = Qs[kk * QS_STRIDE + ty * 4 + i];
#pragma unroll
            for (int j = 0; j < 4; j++) rb[j] = KPs[kk * QS_STRIDE + tx * 4 + j];
#pragma unroll
            for (int i = 0; i < 4; i++)
#pragma unroll
                for (int j = 0; j < 4; j++) acc_s[i][j] += ra[i] * rb[j];
        }
        __syncthreads();

        bool diag = (kt == qbase);

#pragma unroll
        for (int i = 0; i < 4; i++) {
            int il = ty * 4 + i;
            float rmax = -1e30f;
#pragma unroll
            for (int j = 0; j < 4; j++) {
                int jl = tx * 4 + j;
                bool ok = (ms[jl] != 0) && (!diag || jl <= il);
                float s = ok ? acc_s[i][j] : -1e30f;
                acc_s[i][j] = s;
                rmax = fmaxf(rmax, s);
            }
#pragma unroll
            for (int off = 8; off >= 1; off >>= 1)
                rmax = fmaxf(rmax, __shfl_xor_sync(0xffffffffu, rmax, off, 16));
            float m_new = fmaxf(m_r[i], rmax);
            float rsum = 0.f;
#pragma unroll
            for (int j = 0; j < 4; j++) {
                float p = __expf(acc_s[i][j] - m_new);
                acc_s[i][j] = p;
                rsum += p;
            }
#pragma unroll
            for (int off = 8; off >= 1; off >>= 1)
                rsum += __shfl_xor_sync(0xffffffffu, rsum, off, 16);
            float scale = __expf(m_r[i] - m_new);
            l_r[i] = l_r[i] * scale + rsum;
            m_r[i] = m_new;
#pragma unroll
            for (int j = 0; j < 4; j++) acc_o[i][j] *= scale;
        }

#pragma unroll
        for (int i = 0; i < 4; i++)
#pragma unroll
            for (int j = 0; j < 4; j++)
                KPs[(ty * 4 + i) * QS_STRIDE + tx * 4 + j] = acc_s[i][j];
        __syncthreads();

        for (int j = 0; j < 64; j++) {
            float4 vb = *(const float4*)&Vs[j * VS_STRIDE + tx * 4];
            float pa[4];
#pragma unroll
            for (int i = 0; i < 4; i++) pa[i] = KPs[(ty * 4 + i) * QS_STRIDE + j];
#pragma unroll
            for (int i = 0; i < 4; i++) {
                acc_o[i][0] += pa[i] * vb.x;
                acc_o[i][1] += pa[i] * vb.y;
                acc_o[i][2] += pa[i] * vb.z;
                acc_o[i][3] += pa[i] * vb.w;
            }
        }
    }

#pragma unroll
    for (int i = 0; i < 4; i++) {
        int il = ty * 4 + i;
        float inv = (l_r[i] > 0.f) ? (1.0f / l_r[i]) : 0.f;
        float4 o4;
        o4.x = acc_o[i][0] * inv;
        o4.y = acc_o[i][1] * inv;
        o4.z = acc_o[i][2] * inv;
        o4.w = acc_o[i][3] * inv;
        *(float4*)(Out + ((size_t)(b * TT + qbase + il)) * DD + h * DH + tx * 4) = o4;
    }
}

// ---------------------------------------------------------------------------
extern "C" void kernel_launch(void* const* d_in, const int* in_sizes, int n_in,
                              void* d_out, int out_size) {
    const float* x     = (const float*)d_in[0];
    const int*   amask = (const int*)d_in[1];
    const float* Wqkv  = (const float*)d_in[2];
    const float* bqkv  = (const float*)d_in[3];
    const float* Wout  = (const float*)d_in[4];
    const float* bout  = (const float*)d_in[5];
    float* out = (float*)d_out;

    float *qkv, *Qp, *Kp, *Vp, *Att;
    cudaGetSymbolAddress((void**)&qkv, g_qkv);
    cudaGetSymbolAddress((void**)&Qp,  g_q);
    cudaGetSymbolAddress((void**)&Kp,  g_k);
    cudaGetSymbolAddress((void**)&Vp,  g_v);
    cudaGetSymbolAddress((void**)&Att, g_att);

    static bool attr_set = false;
    if (!attr_set) {
        cudaFuncSetAttribute(flash_attn_tiled,
                             cudaFuncAttributeMaxDynamicSharedMemorySize,
                             SMEM_FLASH);
        attr_set = true;
    }

    // 1) QKV projection (tf32 tensor cores)
    {
        dim3 grid(3 * DD / BNg, BT / BMg);
        gemm_tf32_bias<<<grid, 256>>>(x, Wqkv, bqkv, qkv, BT, 3 * DD, DD);
    }
    // 2) RoPE + split
    {
        int total = BB * TT * HH * (DH / 2);
        rope_split_kernel<<<(total + 255) / 256, 256>>>(qkv, Qp, Kp, Vp);
    }
    // 3) Tiled flash attention
    {
        dim3 grid(TT / 64, HH, BB);
        flash_attn_tiled<<<grid, 256, SMEM_FLASH>>>(Qp, Kp, Vp, amask, Att);
    }
    // 4) Output projection (tf32 tensor cores)
    {
        dim3 grid(DD / BNg, BT / BMg);
        gemm_tf32_bias<<<grid, 256>>>(Att, Wout, bout, out, BT, DD, DD);
    }
}

// round 5
// speedup vs baseline: 1.7111x; 1.1326x over previous
#include <cuda_runtime.h>
#include <stdint.h>
#include <math.h>
#include <mma.h>

using namespace nvcuda;

#define BB 2
#define TT 2048
#define DD 1024
#define HH 16
#define DH 64
#define BT (BB*TT)

// Scratch (allocation-free rule: __device__ globals)
__device__ float g_qkv[(size_t)BT * 3 * DD];
__device__ float g_q[(size_t)BT * DD];   // [B,H,T,DH]
__device__ float g_k[(size_t)BT * DD];
__device__ float g_v[(size_t)BT * DD];
__device__ float g_att[(size_t)BT * DD]; // [B*T, D]

// ---------------------------------------------------------------------------
// cp.async helpers
// ---------------------------------------------------------------------------
__device__ __forceinline__ void cp_async16(void* dst, const void* src) {
    unsigned int d = (unsigned int)__cvta_generic_to_shared(dst);
    asm volatile("cp.async.ca.shared.global [%0], [%1], 16;\n" :: "r"(d), "l"(src));
}
__device__ __forceinline__ void cp_commit() {
    asm volatile("cp.async.commit_group;\n");
}
__device__ __forceinline__ void cp_wait1() {
    asm volatile("cp.async.wait_group 1;\n");
}

// ---------------------------------------------------------------------------
// TF32 tensor-core GEMM: C[M,N] = A[M,K] @ B[K,N] + bias[N]
// 128x128 CTA tile, 8 warps (4x2), warp tile 32x64 = 2x4 wmma 16x16x8 frags.
// BK=16, 3-stage cp.async pipeline, 2 CTAs/SM.
// ---------------------------------------------------------------------------
#define BMg 128
#define BNg 128
#define BKg 16
#define STAGES 3
#define A_STRIDE (BKg + 4)   // 20 floats = 80B (16B multiple)
#define B_STRIDE (BNg + 4)   // 132 floats = 528B (16B multiple)
#define AS_TILE (BMg * A_STRIDE)
#define BS_TILE (BKg * B_STRIDE)
#define SMEM_GEMM ((STAGES * (AS_TILE + BS_TILE)) * 4)

__global__ __launch_bounds__(256, 2)
void gemm_tf32_bias(const float* __restrict__ A, const float* __restrict__ B,
                    const float* __restrict__ bias, float* __restrict__ C,
                    int M, int N, int K) {
    extern __shared__ float smg[];
    float* AsBase = smg;                       // [STAGES][BMg][A_STRIDE]
    float* BsBase = smg + STAGES * AS_TILE;    // [STAGES][BKg][B_STRIDE]

    int tid  = threadIdx.x;
    int wid  = tid >> 5;
    int lane = tid & 31;
    int warp_m = wid & 3;        // 0..3 -> 32 rows each
    int warp_n = wid >> 2;       // 0..1 -> 64 cols each
    int brow = blockIdx.y * BMg;
    int bcol = blockIdx.x * BNg;

    int a_row = tid >> 1;          // 0..127
    int a_col = (tid & 1) * 8;     // 0 or 8
    int b_row = tid >> 4;          // 0..15
    int b_col = (tid & 15) * 8;    // 0..120

    const float* Ap = A + (size_t)(brow + a_row) * K + a_col;
    const float* Bp = B + (size_t)b_row * N + bcol + b_col;

    wmma::fragment<wmma::accumulator, 16, 16, 8, float> acc[2][4];
#pragma unroll
    for (int i = 0; i < 2; i++)
#pragma unroll
        for (int j = 0; j < 4; j++) wmma::fill_fragment(acc[i][j], 0.0f);

    const int iters = K / BKg;

    // Prologue: stage 0..STAGES-2
#pragma unroll
    for (int s = 0; s < STAGES - 1; s++) {
        int k0 = s * BKg;
        float* As = AsBase + s * AS_TILE;
        float* Bs = BsBase + s * BS_TILE;
        cp_async16(&As[a_row * A_STRIDE + a_col],     Ap + k0);
        cp_async16(&As[a_row * A_STRIDE + a_col + 4], Ap + k0 + 4);
        cp_async16(&Bs[b_row * B_STRIDE + b_col],     Bp + (size_t)k0 * N);
        cp_async16(&Bs[b_row * B_STRIDE + b_col + 4], Bp + (size_t)k0 * N + 4);
        cp_commit();
    }

    for (int it = 0; it < iters; it++) {
        cp_wait1();
        __syncthreads();

        int buf = it % STAGES;
        float* As = AsBase + buf * AS_TILE;
        float* Bs = BsBase + buf * BS_TILE;

#pragma unroll
        for (int kk = 0; kk < BKg; kk += 8) {
            wmma::fragment<wmma::matrix_a, 16, 16, 8, wmma::precision::tf32, wmma::row_major> af[2];
            wmma::fragment<wmma::matrix_b, 16, 16, 8, wmma::precision::tf32, wmma::row_major> bf[4];
#pragma unroll
            for (int i = 0; i < 2; i++) {
                wmma::load_matrix_sync(af[i], &As[(warp_m * 32 + i * 16) * A_STRIDE + kk], A_STRIDE);
#pragma unroll
                for (int t = 0; t < af[i].num_elements; t++)
                    af[i].x[t] = wmma::__float_to_tf32(af[i].x[t]);
            }
#pragma unroll
            for (int j = 0; j < 4; j++) {
                wmma::load_matrix_sync(bf[j], &Bs[kk * B_STRIDE + warp_n * 64 + j * 16], B_STRIDE);
#pragma unroll
                for (int t = 0; t < bf[j].num_elements; t++)
                    bf[j].x[t] = wmma::__float_to_tf32(bf[j].x[t]);
            }
#pragma unroll
            for (int i = 0; i < 2; i++)
#pragma unroll
                for (int j = 0; j < 4; j++)
                    wmma::mma_sync(acc[i][j], af[i], bf[j], acc[i][j]);
        }

        int k_next = (it + STAGES - 1) * BKg;
        if (k_next < K) {
            int s = (it + STAGES - 1) % STAGES;
            float* Asn = AsBase + s * AS_TILE;
            float* Bsn = BsBase + s * BS_TILE;
            cp_async16(&Asn[a_row * A_STRIDE + a_col],     Ap + k_next);
            cp_async16(&Asn[a_row * A_STRIDE + a_col + 4], Ap + k_next + 4);
            cp_async16(&Bsn[b_row * B_STRIDE + b_col],     Bp + (size_t)k_next * N);
            cp_async16(&Bsn[b_row * B_STRIDE + b_col + 4], Bp + (size_t)k_next * N + 4);
        }
        cp_commit();   // commit every iter (possibly empty) keeps wait_group count consistent
    }

    // Epilogue: stage each 16x16 fragment through smem, add bias, write global
    __syncthreads();
    float* stg = AsBase + wid * 16 * 24;

    int er = lane >> 1;            // 0..15
    int ec = (lane & 1) * 8;       // 0 or 8
#pragma unroll
    for (int i = 0; i < 2; i++) {
#pragma unroll
        for (int j = 0; j < 4; j++) {
            wmma::store_matrix_sync(stg, acc[i][j], 24, wmma::mem_row_major);
            __syncwarp();
            int gr = brow + warp_m * 32 + i * 16 + er;
            int gc = bcol + warp_n * 64 + j * 16 + ec;
            float4 v0 = *(float4*)&stg[er * 24 + ec];
            float4 v1 = *(float4*)&stg[er * 24 + ec + 4];
            const float4 bb0 = *(const float4*)&bias[gc];
            const float4 bb1 = *(const float4*)&bias[gc + 4];
            v0.x += bb0.x; v0.y += bb0.y; v0.z += bb0.z; v0.w += bb0.w;
            v1.x += bb1.x; v1.y += bb1.y; v1.z += bb1.z; v1.w += bb1.w;
            *(float4*)(C + (size_t)gr * N + gc)     = v0;
            *(float4*)(C + (size_t)gr * N + gc + 4) = v1;
            __syncwarp();
        }
    }
}

// ---------------------------------------------------------------------------
// RoPE + split qkv[BT, 3D] -> Q,K,V in [B,H,T,DH]
// ---------------------------------------------------------------------------
__global__ __launch_bounds__(256)
void rope_split_kernel(const float* __restrict__ qkv,
                       float* __restrict__ Q, float* __restrict__ K,
                       float* __restrict__ V) {
    int idx = blockIdx.x * blockDim.x + threadIdx.x;
    const int total = BB * TT * HH * (DH / 2);
    if (idx >= total) return;
    int d2 = idx & 31;
    int h  = (idx >> 5) & (HH - 1);
    int t  = (idx >> 9) & (TT - 1);
    int b  = idx >> 20;

    size_t row = (size_t)b * TT + t;
    const float* qr = qkv + row * (3 * DD) + h * DH + 2 * d2;
    const float* kr = qr + DD;
    const float* vr = qr + 2 * DD;

    float inv_freq = powf(10000.0f, -((float)(2 * d2)) / (float)DH);
    float freq = (float)t * inv_freq;
    float s = sinf(freq);
    float c = cosf(freq);

    float qe = qr[0], qo = qr[1];
    float ke = kr[0], ko = kr[1];

    size_t o = ((((size_t)b * HH + h) * TT) + t) * DH + 2 * d2;
    Q[o]     = qe * c - qo * s;
    Q[o + 1] = qe * s + qo * c;
    K[o]     = ke * c - ko * s;
    K[o + 1] = ke * s + ko * c;
    V[o]     = vr[0];
    V[o + 1] = vr[1];
}

// ---------------------------------------------------------------------------
// Tiled flash attention: 64-query tile per block, 256 threads. (unchanged)
// ---------------------------------------------------------------------------
#define QS_STRIDE 65
#define VS_STRIDE 68
#define SMEM_FLASH ((2 * 64 * QS_STRIDE + 64 * VS_STRIDE) * 4 + 64 * 4)

__device__ __forceinline__ void load_tile_T(const float* __restrict__ src,
                                            float* __restrict__ dst,
                                            int tid, float mul) {
    int r = tid >> 2;
    int cbase = (tid & 3) * 4;
#pragma unroll
    for (int rep = 0; rep < 4; rep++) {
        int c = cbase + rep * 16;
        float4 v = *(const float4*)(src + r * 64 + c);
        dst[(c + 0) * QS_STRIDE + r] = v.x * mul;
        dst[(c + 1) * QS_STRIDE + r] = v.y * mul;
        dst[(c + 2) * QS_STRIDE + r] = v.z * mul;
        dst[(c + 3) * QS_STRIDE + r] = v.w * mul;
    }
}

__global__ __launch_bounds__(256)
void flash_attn_tiled(const float* __restrict__ Q, const float* __restrict__ K,
                      const float* __restrict__ V, const int* __restrict__ mask,
                      float* __restrict__ Out) {
    extern __shared__ float sm[];
    float* Qs  = sm;
    float* KPs = sm + 64 * QS_STRIDE;
    float* Vs  = sm + 2 * 64 * QS_STRIDE;
    int*   ms  = (int*)(sm + 2 * 64 * QS_STRIDE + 64 * VS_STRIDE);

    int b = blockIdx.z, h = blockIdx.y;
    int qtile = gridDim.x - 1 - blockIdx.x;
    int qbase = qtile * 64;
    int tid = threadIdx.x;
    int ty = tid >> 4;
    int tx = tid & 15;

    const size_t bh = ((size_t)b * HH + h) * TT;
    const float* Qb = Q + bh * DH;
    const float* Kb = K + bh * DH;
    const float* Vb = V + bh * DH;

    load_tile_T(Qb + (size_t)qbase * DH, Qs, tid, 0.125f);

    float acc_o[4][4];
    float m_r[4], l_r[4];
#pragma unroll
    for (int i = 0; i < 4; i++) {
        m_r[i] = -1e30f;
        l_r[i] = 0.f;
#pragma unroll
        for (int j = 0; j < 4; j++) acc_o[i][j] = 0.f;
    }

    for (int kt = 0; kt <= qbase; kt += 64) {
        __syncthreads();

        load_tile_T(Kb + (size_t)kt * DH, KPs, tid, 1.0f);
        {
            int j = tid >> 4;
            int c = (tid & 15) * 4;
#pragma unroll
            for (int rep = 0; rep < 4; rep++) {
                float4 v = *(const float4*)(Vb + (size_t)(kt + j + rep * 16) * DH + c);
                *(float4*)&Vs[(j + rep * 16) * VS_STRIDE + c] = v;
            }
        }
        if (tid < 64) ms[tid] = mask[b * TT + kt + tid];
        __syncthreads();

        float acc_s[4][4];
#pragma unroll
        for (int i = 0; i < 4; i++)
#pragma unroll
            for (int j = 0; j < 4; j++) acc_s[i][j] = 0.f;

        for (int kk = 0; kk < 64; kk++) {
            float ra[4], rb[4];
#pragma unroll
            for (int i = 0; i < 4; i++) ra[i] = Qs[kk * QS_STRIDE + ty * 4 + i];
#pragma unroll
            for (int j = 0; j < 4; j++) rb[j] = KPs[kk * QS_STRIDE + tx * 4 + j];
#pragma unroll
            for (int i = 0; i < 4; i++)
#pragma unroll
                for (int j = 0; j < 4; j++) acc_s[i][j] += ra[i] * rb[j];
        }
        __syncthreads();

        bool diag = (kt == qbase);

#pragma unroll
        for (int i = 0; i < 4; i++) {
            int il = ty * 4 + i;
            float rmax = -1e30f;
#pragma unroll
            for (int j = 0; j < 4; j++) {
                int jl = tx * 4 + j;
                bool ok = (ms[jl] != 0) && (!diag || jl <= il);
                float s = ok ? acc_s[i][j] : -1e30f;
                acc_s[i][j] = s;
                rmax = fmaxf(rmax, s);
            }
#pragma unroll
            for (int off = 8; off >= 1; off >>= 1)
                rmax = fmaxf(rmax, __shfl_xor_sync(0xffffffffu, rmax, off, 16));
            float m_new = fmaxf(m_r[i], rmax);
            float rsum = 0.f;
#pragma unroll
            for (int j = 0; j < 4; j++) {
                float p = __expf(acc_s[i][j] - m_new);
                acc_s[i][j] = p;
                rsum += p;
            }
#pragma unroll
            for (int off = 8; off >= 1; off >>= 1)
                rsum += __shfl_xor_sync(0xffffffffu, rsum, off, 16);
            float scale = __expf(m_r[i] - m_new);
            l_r[i] = l_r[i] * scale + rsum;
            m_r[i] = m_new;
#pragma unroll
            for (int j = 0; j < 4; j++) acc_o[i][j] *= scale;
        }

#pragma unroll
        for (int i = 0; i < 4; i++)
#pragma unroll
            for (int j = 0; j < 4; j++)
                KPs[(ty * 4 + i) * QS_STRIDE + tx * 4 + j] = acc_s[i][j];
        __syncthreads();

        for (int j = 0; j < 64; j++) {
            float4 vb = *(const float4*)&Vs[j * VS_STRIDE + tx * 4];
            float pa[4];
#pragma unroll
            for (int i = 0; i < 4; i++) pa[i] = KPs[(ty * 4 + i) * QS_STRIDE + j];
#pragma unroll
            for (int i = 0; i < 4; i++) {
                acc_o[i][0] += pa[i] * vb.x;
                acc_o[i][1] += pa[i] * vb.y;
                acc_o[i][2] += pa[i] * vb.z;
                acc_o[i][3] += pa[i] * vb.w;
            }
        }
    }

#pragma unroll
    for (int i = 0; i < 4; i++) {
        int il = ty * 4 + i;
        float inv = (l_r[i] > 0.f) ? (1.0f / l_r[i]) : 0.f;
        float4 o4;
        o4.x = acc_o[i][0] * inv;
        o4.y = acc_o[i][1] * inv;
        o4.z = acc_o[i][2] * inv;
        o4.w = acc_o[i][3] * inv;
        *(float4*)(Out + ((size_t)(b * TT + qbase + il)) * DD + h * DH + tx * 4) = o4;
    }
}

// ---------------------------------------------------------------------------
extern "C" void kernel_launch(void* const* d_in, const int* in_sizes, int n_in,
                              void* d_out, int out_size) {
    const float* x     = (const float*)d_in[0];
    const int*   amask = (const int*)d_in[1];
    const float* Wqkv  = (const float*)d_in[2];
    const float* bqkv  = (const float*)d_in[3];
    const float* Wout  = (const float*)d_in[4];
    const float* bout  = (const float*)d_in[5];
    float* out = (float*)d_out;

    float *qkv, *Qp, *Kp, *Vp, *Att;
    cudaGetSymbolAddress((void**)&qkv, g_qkv);
    cudaGetSymbolAddress((void**)&Qp,  g_q);
    cudaGetSymbolAddress((void**)&Kp,  g_k);
    cudaGetSymbolAddress((void**)&Vp,  g_v);
    cudaGetSymbolAddress((void**)&Att, g_att);

    static bool attr_set = false;
    if (!attr_set) {
        cudaFuncSetAttribute(flash_attn_tiled,
                             cudaFuncAttributeMaxDynamicSharedMemorySize,
                             SMEM_FLASH);
        cudaFuncSetAttribute(gemm_tf32_bias,
                             cudaFuncAttributeMaxDynamicSharedMemorySize,
                             SMEM_GEMM);
        attr_set = true;
    }

    // 1) QKV projection (tf32 tensor cores, cp.async pipeline)
    {
        dim3 grid(3 * DD / BNg, BT / BMg);
        gemm_tf32_bias<<<grid, 256, SMEM_GEMM>>>(x, Wqkv, bqkv, qkv, BT, 3 * DD, DD);
    }
    // 2) RoPE + split
    {
        int total = BB * TT * HH * (DH / 2);
        rope_split_kernel<<<(total + 255) / 256, 256>>>(qkv, Qp, Kp, Vp);
    }
    // 3) Tiled flash attention
    {
        dim3 grid(TT / 64, HH, BB);
        flash_attn_tiled<<<grid, 256, SMEM_FLASH>>>(Qp, Kp, Vp, amask, Att);
    }
    // 4) Output projection (tf32 tensor cores, cp.async pipeline)
    {
        dim3 grid(DD / BNg, BT / BMg);
        gemm_tf32_bias<<<grid, 256, SMEM_GEMM>>>(Att, Wout, bout, out, BT, DD, DD);
    }
}